// round 15
// baseline (speedup 1.0000x reference)
#include <cuda_runtime.h>
#include <cuda_fp16.h>
#include <cstdint>
#include <math.h>

#define SEQ   4096
#define DIM   512
#define KCONV 3
#define KTOT  1536
#define MAXOUT 16384
#define LN_EPS 1e-5f
#define BK    64
#define NKT   (KTOT / BK)            // 24 k-tiles
#define ATB   8192                   // A limb tile: 64 rows x 128 B
#define BTB   16384                  // B limb tile: 128 rows x 128 B
#define BUFB  (2 * ATB + 2 * BTB)    // 48 KB per stage
#define SMEM_DYN (2 * BUFB)          // 96 KB double-buffered -> 2 CTAs/SM
#define WSCALE 256.0f
#define WINV   (1.0f / 256.0f)

// -------- scratch (no allocations allowed) --------
__device__ __half g_e[2][SEQ * DIM];        // enc limbs (fp16 x2)
__device__ __half g_xs[2][SEQ * DIM];       // x1 limbs
__device__ __half g_Bw[2][2][DIM * KTOT];   // weight limbs [conv][limb][n*1536+c], pre-scaled x256
__device__ float g_y[SEQ * DIM];            // conv output (fp32)
__device__ int   g_dur[SEQ];
__device__ int   g_cum[SEQ];

static __device__ __forceinline__ uint32_t smem_u32(const void* p) {
    uint32_t a;
    asm("{ .reg .u64 t; cvta.to.shared.u64 t, %1; cvt.u32.u64 %0, t; }"
        : "=r"(a) : "l"(p));
    return a;
}

static __device__ __forceinline__ void split2(float v, __half& h0, __half& h1) {
    h0 = __float2half_rn(v);
    h1 = __float2half_rn(v - __half2float(h0));
}

// ============================================================
// enc fp32 -> 2 fp16 limb arrays. float4/thread.
// ============================================================
__global__ void split_enc_kernel(const float* __restrict__ e) {
    int i = blockIdx.x * 256 + threadIdx.x;        // float4 index
    float4 v = ((const float4*)e)[i];
    float a[4] = {v.x, v.y, v.z, v.w};
    __half h0[4], h1[4];
#pragma unroll
    for (int j = 0; j < 4; j++) split2(a[j], h0[j], h1[j]);
    __half2 t;
    t.x = h0[0]; t.y = h0[1]; ((__half2*)g_e[0])[i * 2] = t;
    t.x = h0[2]; t.y = h0[3]; ((__half2*)g_e[0])[i * 2 + 1] = t;
    t.x = h1[0]; t.y = h1[1]; ((__half2*)g_e[1])[i * 2] = t;
    t.x = h1[2]; t.y = h1[3]; ((__half2*)g_e[1])[i * 2 + 1] = t;
}

// ============================================================
// weights: w[o][d][k]*256 -> limbs at [o][c], c = k*512+d (K-major rows)
// ============================================================
__global__ void wsplit_kernel(const float* __restrict__ w1,
                              const float* __restrict__ w2) {
    int idx = blockIdx.x * 256 + threadIdx.x;      // o*1536 + c
    int conv = blockIdx.y;
    const float* w = conv ? w2 : w1;
    int o = idx / KTOT;
    int c = idx - o * KTOT;
    int k = c >> 9;
    int d = c & 511;
    float v = w[o * KTOT + d * KCONV + k] * WSCALE;
    __half h0, h1;
    split2(v, h0, h1);
    g_Bw[conv][0][idx] = h0;
    g_Bw[conv][1][idx] = h1;
}

// ---------------- mma.sync building blocks (sm_80 class) ----------------
static __device__ __forceinline__ void ldsm4(uint32_t& r0, uint32_t& r1,
                                             uint32_t& r2, uint32_t& r3,
                                             uint32_t addr) {
    asm volatile("ldmatrix.sync.aligned.m8n8.x4.shared.b16 {%0,%1,%2,%3}, [%4];"
                 : "=r"(r0), "=r"(r1), "=r"(r2), "=r"(r3) : "r"(addr));
}
static __device__ __forceinline__ void mma16816(float* c, const uint32_t* a,
                                                uint32_t b0, uint32_t b1) {
    asm volatile(
        "mma.sync.aligned.m16n8k16.row.col.f32.f16.f16.f32 "
        "{%0,%1,%2,%3}, {%4,%5,%6,%7}, {%8,%9}, {%0,%1,%2,%3};"
        : "+f"(c[0]), "+f"(c[1]), "+f"(c[2]), "+f"(c[3])
        : "r"(a[0]), "r"(a[1]), "r"(a[2]), "r"(a[3]), "r"(b0), "r"(b1));
}
static __device__ __forceinline__ void cp16(uint32_t dst, const void* src,
                                            uint32_t srcsz) {
    asm volatile("cp.async.ca.shared.global [%0], [%1], 16, %2;"
                 :: "r"(dst), "l"(src), "r"(srcsz) : "memory");
}

// ============================================================
// Conv-as-GEMM on mma.sync (HMMA), fp16x2 limbs: full product
// (a0+a1)(b0+b1) = 4 MMA products, fp32 accumulate, x(1/256) epilogue.
// BM=64, BN=128, BK=64, 256 threads (8 warps, each 32Mx32N).
// grid (64, 4) = 256 CTAs -> 2 CTAs/SM (96 KB smem each).
// ============================================================
template <int PASS>
__global__ __launch_bounds__(256, 2)
void conv_mma_kernel() {
    extern __shared__ char ds[];
    const uint32_t sBase = smem_u32(ds);

    const int tid = threadIdx.x;
    const int wid = tid >> 5;
    const int lane = tid & 31;
    const int bm = blockIdx.x * 64;
    const int bn = blockIdx.y * 128;

    const int wm = wid >> 2;        // 0..1  -> M offset wm*32
    const int wn = wid & 3;         // 0..3  -> N offset wn*32

    float acc[2][4][4];
#pragma unroll
    for (int i = 0; i < 2; i++)
#pragma unroll
        for (int j = 0; j < 4; j++)
#pragma unroll
            for (int q = 0; q < 4; q++) acc[i][j][q] = 0.f;

    // ---- tile loader: k-tile t24 -> buffer bi (2 A limb + 2 B limb tiles)
    auto load_tile = [&](int t24, int bi) {
        const int k0 = t24 * BK;
        const int kseg  = k0 >> 9;
        const int dbase = k0 & 511;
        const uint32_t buf = sBase + bi * BUFB;
        // 3072 16B-chunks over 256 threads = 12 each
#pragma unroll
        for (int i = 0; i < 12; i++) {
            int cid = tid + i * 256;          // 0..3071
            if (cid < 1024) {                 // A limbs: 2 x 64 rows x 8 chunks
                int limb = cid >> 9;
                int w = cid & 511;
                int r = w >> 3, c = w & 7;
                uint32_t dst = buf + limb * ATB + r * 128 + ((c ^ (r & 7)) * 16);
                int srow = bm + r + kseg - 1;
                uint32_t ok = (srow >= 0 && srow < SEQ) ? 16u : 0u;
                int srowc = srow < 0 ? 0 : (srow >= SEQ ? SEQ - 1 : srow);
                const __half* limbA = PASS ? g_xs[limb] : g_e[limb];
                cp16(dst, limbA + ((long long)srowc * DIM + dbase + c * 8), ok);
            } else {                          // B limbs: 2 x 128 rows x 8 chunks
                int bidx = cid - 1024;
                int limb = bidx >> 10;
                int w = bidx & 1023;
                int r = w >> 3, c = w & 7;
                uint32_t dst = buf + 2 * ATB + limb * BTB + r * 128 +
                               ((c ^ (r & 7)) * 16);
                const __half* limbB = g_Bw[PASS][limb];
                cp16(dst, limbB + ((long long)(bn + r) * KTOT + k0 + c * 8), 16u);
            }
        }
        asm volatile("cp.async.commit_group;" ::: "memory");
    };

    // prologue
    load_tile(0, 0);

    const int rr = lane & 7;
    const int q  = lane >> 3;

#pragma unroll 1
    for (int t = 0; t < NKT; ++t) {
        const int bi = t & 1;
        if (t + 1 < NKT) {
            load_tile(t + 1, bi ^ 1);
            asm volatile("cp.async.wait_group 1;" ::: "memory");
        } else {
            asm volatile("cp.async.wait_group 0;" ::: "memory");
        }
        __syncthreads();

        const uint32_t buf = sBase + bi * BUFB;
#pragma unroll
        for (int ks = 0; ks < 4; ks++) {
            // A frags for both limbs, 2 m16 tiles each
            uint32_t a[2][2][4];
#pragma unroll
            for (int s = 0; s < 2; s++)
#pragma unroll
                for (int mt = 0; mt < 2; mt++) {
                    int arow = wm * 32 + mt * 16 + rr + (q & 1) * 8;
                    int ach  = 2 * ks + (q >> 1);
                    uint32_t ad = buf + s * ATB + arow * 128 +
                                  ((ach ^ (arow & 7)) * 16);
                    ldsm4(a[s][mt][0], a[s][mt][1], a[s][mt][2], a[s][mt][3], ad);
                }
            // B frags per n16 block and limb; each feeds both A limbs
#pragma unroll
            for (int nt = 0; nt < 2; nt++) {
#pragma unroll
                for (int bl = 0; bl < 2; bl++) {
                    int brow = wn * 32 + nt * 16 + rr + (q >> 1) * 8;
                    int bch  = 2 * ks + (q & 1);
                    uint32_t bd = buf + 2 * ATB + bl * BTB + brow * 128 +
                                  ((bch ^ (brow & 7)) * 16);
                    uint32_t b0, b1, b2, b3;
                    ldsm4(b0, b1, b2, b3, bd);
#pragma unroll
                    for (int al = 0; al < 2; al++)
#pragma unroll
                        for (int mt = 0; mt < 2; mt++) {
                            mma16816(acc[mt][nt * 2],     a[al][mt], b0, b1);
                            mma16816(acc[mt][nt * 2 + 1], a[al][mt], b2, b3);
                        }
                }
            }
        }
        __syncthreads();
    }

    // ---- epilogue: undo weight pre-scale, write fp32 to g_y
#pragma unroll
    for (int mt = 0; mt < 2; mt++) {
#pragma unroll
        for (int j = 0; j < 4; j++) {
            int row = bm + wm * 32 + mt * 16 + (lane >> 2);
            int col = bn + wn * 32 + j * 8 + (lane & 3) * 2;
            float2 v0, v1;
            v0.x = acc[mt][j][0] * WINV; v0.y = acc[mt][j][1] * WINV;
            v1.x = acc[mt][j][2] * WINV; v1.y = acc[mt][j][3] * WINV;
            *(float2*)&g_y[(long long)row * DIM + col] = v0;
            *(float2*)&g_y[(long long)(row + 8) * DIM + col] = v1;
        }
    }
}

// ------------- block reduction helper (128 threads) -------------
__device__ __forceinline__ void reduce2_128(float& s, float& q, float* sh) {
#pragma unroll
    for (int off = 16; off; off >>= 1) {
        s += __shfl_down_sync(0xFFFFFFFFu, s, off);
        q += __shfl_down_sync(0xFFFFFFFFu, q, off);
    }
    int w = threadIdx.x >> 5;
    if ((threadIdx.x & 31) == 0) { sh[w] = s; sh[4 + w] = q; }
    __syncthreads();
    s = sh[0] + sh[1] + sh[2] + sh[3];
    q = sh[4] + sh[5] + sh[6] + sh[7];
}

// ============================================================
// bias + LN1 + ReLU: g_y -> x1 limbs (fp16 x2)
// ============================================================
__global__ __launch_bounds__(128)
void ln_relu_kernel(const float* __restrict__ g,
                    const float* __restrict__ b,
                    const float* __restrict__ cb) {
    __shared__ float sh[8];
    int row = blockIdx.x;
    int tid = threadIdx.x;
    float4 y = ((const float4*)(g_y + (long long)row * DIM))[tid];
    float4 cbv = ((const float4*)cb)[tid];
    float4 v;
    v.x = y.x + cbv.x; v.y = y.y + cbv.y; v.z = y.z + cbv.z; v.w = y.w + cbv.w;
    float s = v.x + v.y + v.z + v.w;
    float q = v.x * v.x + v.y * v.y + v.z * v.z + v.w * v.w;
    reduce2_128(s, q, sh);
    float mean = s * (1.f / DIM);
    float var  = q * (1.f / DIM) - mean * mean;
    float rstd = rsqrtf(var + LN_EPS);
    float4 gg = ((const float4*)g)[tid];
    float4 bb = ((const float4*)b)[tid];
    float ov[4];
    ov[0] = fmaxf((v.x - mean) * rstd * gg.x + bb.x, 0.f);
    ov[1] = fmaxf((v.y - mean) * rstd * gg.y + bb.y, 0.f);
    ov[2] = fmaxf((v.z - mean) * rstd * gg.z + bb.z, 0.f);
    ov[3] = fmaxf((v.w - mean) * rstd * gg.w + bb.w, 0.f);
    __half h0[4], h1[4];
#pragma unroll
    for (int j = 0; j < 4; j++) split2(ov[j], h0[j], h1[j]);
    long long pbase = ((long long)row * DIM) / 2 + tid * 2;
    __half2 t;
    t.x = h0[0]; t.y = h0[1]; ((__half2*)g_xs[0])[pbase] = t;
    t.x = h0[2]; t.y = h0[3]; ((__half2*)g_xs[0])[pbase + 1] = t;
    t.x = h1[0]; t.y = h1[1]; ((__half2*)g_xs[1])[pbase] = t;
    t.x = h1[2]; t.y = h1[3]; ((__half2*)g_xs[1])[pbase + 1] = t;
}

// ============================================================
// bias + LN2 + ReLU + linear + duration -> g_dur
// ============================================================
__global__ __launch_bounds__(128)
void ln_dur_kernel(const float* __restrict__ g,
                   const float* __restrict__ b,
                   const float* __restrict__ lw,
                   const float* __restrict__ lb,
                   const float* __restrict__ cb) {
    __shared__ float sh[8];
    int row = blockIdx.x;
    int tid = threadIdx.x;
    float4 y = ((const float4*)(g_y + (long long)row * DIM))[tid];
    float4 cbv = ((const float4*)cb)[tid];
    float4 v;
    v.x = y.x + cbv.x; v.y = y.y + cbv.y; v.z = y.z + cbv.z; v.w = y.w + cbv.w;
    float s = v.x + v.y + v.z + v.w;
    float q = v.x * v.x + v.y * v.y + v.z * v.z + v.w * v.w;
    reduce2_128(s, q, sh);
    float mean = s * (1.f / DIM);
    float var  = q * (1.f / DIM) - mean * mean;
    float rstd = rsqrtf(var + LN_EPS);
    float4 gg = ((const float4*)g)[tid];
    float4 bb = ((const float4*)b)[tid];
    float4 ww = ((const float4*)lw)[tid];
    float ox = fmaxf((v.x - mean) * rstd * gg.x + bb.x, 0.f);
    float oy = fmaxf((v.y - mean) * rstd * gg.y + bb.y, 0.f);
    float oz = fmaxf((v.z - mean) * rstd * gg.z + bb.z, 0.f);
    float ow = fmaxf((v.w - mean) * rstd * gg.w + bb.w, 0.f);
    float t = ox * ww.x + oy * ww.y + oz * ww.z + ow * ww.w;
    __syncthreads();
    float dummy = 0.f;
    reduce2_128(t, dummy, sh);
    if (tid == 0) {
        float pred = fmaxf(t + lb[0], 0.f);
        g_dur[row] = (int)floorf(pred + 0.5f);
    }
}

// ============================================================
// Inclusive cumsum of g_dur (4096 ints), single block.
// ============================================================
__global__ __launch_bounds__(1024)
void cumsum_kernel() {
    __shared__ int part[1024];
    int tid = threadIdx.x;
    int v[4];
    int s = 0;
#pragma unroll
    for (int i = 0; i < 4; i++) { v[i] = g_dur[tid * 4 + i]; s += v[i]; }
    part[tid] = s;
    __syncthreads();
    for (int off = 1; off < 1024; off <<= 1) {
        int t = 0;
        if (tid >= off) t = part[tid - off];
        __syncthreads();
        if (tid >= off) part[tid] += t;
        __syncthreads();
    }
    int run = (tid > 0) ? part[tid - 1] : 0;
#pragma unroll
    for (int i = 0; i < 4; i++) { run += v[i]; g_cum[tid * 4 + i] = run; }
}

// ============================================================
// Length regulation: one block per output frame t.
// ============================================================
__global__ __launch_bounds__(128)
void gather_kernel(const float* __restrict__ enc,
                   float* __restrict__ out,
                   float* __restrict__ pos,
                   int write_pos) {
    int t = blockIdx.x;
    int tid = threadIdx.x;
    int total = g_cum[SEQ - 1];
    float4 val = make_float4(0.f, 0.f, 0.f, 0.f);
    if (t < total) {
        int lo = 0, hi = SEQ;
        while (lo < hi) {
            int mid = (lo + hi) >> 1;
            if (g_cum[mid] <= t) lo = mid + 1; else hi = mid;
        }
        if (lo > SEQ - 1) lo = SEQ - 1;
        val = ((const float4*)(enc + (long long)lo * DIM))[tid];
    }
    ((float4*)(out + (long long)t * DIM))[tid] = val;
    if (write_pos && tid == 0) pos[t] = (float)(t + 1);
}

// ============================================================
extern "C" void kernel_launch(void* const* d_in, const int* in_sizes, int n_in,
                              void* d_out, int out_size) {
    const float* enc = (const float*)d_in[0];
    const float* c1w = (const float*)d_in[1];
    const float* c1b = (const float*)d_in[2];
    const float* g1  = (const float*)d_in[3];
    const float* b1  = (const float*)d_in[4];
    const float* c2w = (const float*)d_in[5];
    const float* c2b = (const float*)d_in[6];
    const float* g2  = (const float*)d_in[7];
    const float* b2  = (const float*)d_in[8];
    const float* lw  = (const float*)d_in[9];
    const float* lb  = (const float*)d_in[10];
    float* out = (float*)d_out;

    cudaFuncSetAttribute(conv_mma_kernel<0>,
                         cudaFuncAttributeMaxDynamicSharedMemorySize, SMEM_DYN);
    cudaFuncSetAttribute(conv_mma_kernel<1>,
                         cudaFuncAttributeMaxDynamicSharedMemorySize, SMEM_DYN);

    split_enc_kernel<<<SEQ * DIM / 1024, 256>>>(enc);
    wsplit_kernel<<<dim3(KTOT * DIM / 256, 2), 256>>>(c1w, c2w);
    conv_mma_kernel<0><<<dim3(SEQ / 64, DIM / 128), 256, SMEM_DYN>>>();
    ln_relu_kernel<<<SEQ, 128>>>(g1, b1, c1b);
    conv_mma_kernel<1><<<dim3(SEQ / 64, DIM / 128), 256, SMEM_DYN>>>();
    ln_dur_kernel<<<SEQ, 128>>>(g2, b2, lw, lb, c2b);
    cumsum_kernel<<<1, 1024>>>();

    int write_pos = (out_size >= MAXOUT * DIM + MAXOUT) ? 1 : 0;
    gather_kernel<<<MAXOUT, 128>>>(enc, out, out + (size_t)MAXOUT * DIM, write_pos);
}